// round 5
// baseline (speedup 1.0000x reference)
#include <cuda_runtime.h>
#include <math.h>
#include <stdint.h>

#define N_   8
#define CIN  512
#define MID  256
#define OUTC 256
#define H_   56
#define W_   56
#define P_   3136
#define PY_  784
#define K_   9
#define EPSF 1e-5f

// Scratch (static device globals; no allocation allowed)
__device__ float g_nhwc[(size_t)N_ * P_ * MID];       // xf in NHWC for gather
__device__ float g_off[(size_t)N_ * 18 * P_];         // offsets
__device__ float g_xf_scratch[(size_t)N_ * MID * P_]; // xf NCHW fallback
__device__ float g_wt[(size_t)OUTC * 2304];           // dcn weights, k-major, tf32-rounded

// ---------------------------------------------------------------------------
// helpers (family-safe PTX only: sm_80+ instructions)
// ---------------------------------------------------------------------------
__device__ __forceinline__ float to_tf32(float x) {
    uint32_t u;
    asm("cvt.rna.tf32.f32 %0, %1;" : "=r"(u) : "f"(x));
    return __uint_as_float(u);
}
__device__ __forceinline__ void mma_tf32(float* d, const uint32_t* a, const uint32_t* b) {
    asm volatile(
        "mma.sync.aligned.m16n8k8.row.col.f32.tf32.tf32.f32 "
        "{%0,%1,%2,%3}, {%4,%5,%6,%7}, {%8,%9}, {%0,%1,%2,%3};"
        : "+f"(d[0]), "+f"(d[1]), "+f"(d[2]), "+f"(d[3])
        : "r"(a[0]), "r"(a[1]), "r"(a[2]), "r"(a[3]), "r"(b[0]), "r"(b[1]));
}
__device__ __forceinline__ uint32_t smem_u32(const void* p) {
    uint32_t a;
    asm("{ .reg .u64 t; cvta.to.shared.u64 t, %1; cvt.u32.u64 %0, t; }" : "=r"(a) : "l"(p));
    return a;
}
__device__ __forceinline__ void cp_async16(uint32_t dst, const void* src) {
    asm volatile("cp.async.cg.shared.global [%0], [%1], 16;" :: "r"(dst), "l"(src));
}
#define CP_COMMIT() asm volatile("cp.async.commit_group;" ::: "memory")
#define CP_WAIT0()  asm volatile("cp.async.wait_group 0;" ::: "memory")

// ---------------------------------------------------------------------------
// Kernel 0: transpose dcn weights to k-major [o][kk*256+c], tf32-rounded
// ---------------------------------------------------------------------------
__global__ void k0_wt(const float* __restrict__ dw)
{
    int o = blockIdx.x;
    for (int i = threadIdx.x; i < 2304; i += 256) {
        int kk = i >> 8, c = i & 255;
        g_wt[(size_t)o * 2304 + i] = to_tf32(dw[(size_t)o * 2304 + c * 9 + kk]);
    }
}

// ---------------------------------------------------------------------------
// Kernel 1: conv1(1x1,512->256) + BN1 + nearest-upsample(y) + attention fuse
// (unchanged from R2)
// ---------------------------------------------------------------------------
__global__ __launch_bounds__(256, 3)
void k1_fuse(const float* __restrict__ x, const float* __restrict__ y,
             const float* __restrict__ w1,
             const float* __restrict__ g1, const float* __restrict__ b1,
             const float* __restrict__ mu1, const float* __restrict__ v1,
             const float* __restrict__ attw, const float* __restrict__ attb,
             float* __restrict__ xf_nchw)
{
    extern __shared__ float sm[];
    float* xs   = sm;               // 512
    float* ws   = xs + 512;         // 4352
    float* yu_s = ws + 4352;        // 8448
    float* aw   = yu_s + 8448;      // 1024
    float* red  = aw + 1024;        // 256
    float* zs   = red + 256;        // 64

    const int n   = blockIdx.y;
    const int p0  = blockIdx.x * 32;
    const int tid = threadIdx.x;
    const int mlo = tid & 127;
    const int pb  = (tid >> 7) * 16;
    const int wid = tid >> 5;
    const int lane = tid & 31;

    float acc0[16], acc1[16];
#pragma unroll
    for (int j = 0; j < 16; j++) { acc0[j] = 0.f; acc1[j] = 0.f; }

    for (int i = tid; i < 1024; i += 256) aw[i] = attw[i];

    {
        const float* yb = y + (size_t)n * MID * PY_;
        for (int i = tid; i < 8192; i += 256) {
            int m = i >> 5, p = i & 31;
            int pgl = p0 + p;
            int hh = pgl / 56, ww = pgl % 56;
            int si = (hh >> 1) * 28 + (ww >> 1);
            yu_s[m * 33 + p] = yb[(size_t)m * PY_ + si];
        }
    }

    const float* xb = x + (size_t)n * CIN * P_ + p0;
    for (int c0 = 0; c0 < CIN; c0 += 16) {
        for (int i = tid; i < 512; i += 256) {
            int c = i >> 5, p = i & 31;
            xs[c * 32 + p] = xb[(size_t)(c0 + c) * P_ + p];
        }
        for (int i = tid; i < 4096; i += 256) {
            int m = i >> 4, cc = i & 15;
            ws[m * 17 + cc] = w1[m * 512 + c0 + cc];
        }
        __syncthreads();
#pragma unroll
        for (int cc = 0; cc < 16; cc++) {
            float wv0 = ws[mlo * 17 + cc];
            float wv1 = ws[(mlo + 128) * 17 + cc];
            const float4* xp = (const float4*)(xs + cc * 32 + pb);
#pragma unroll
            for (int u = 0; u < 4; u++) {
                float4 xv = xp[u];
                acc0[u*4+0] = fmaf(wv0, xv.x, acc0[u*4+0]);
                acc0[u*4+1] = fmaf(wv0, xv.y, acc0[u*4+1]);
                acc0[u*4+2] = fmaf(wv0, xv.z, acc0[u*4+2]);
                acc0[u*4+3] = fmaf(wv0, xv.w, acc0[u*4+3]);
                acc1[u*4+0] = fmaf(wv1, xv.x, acc1[u*4+0]);
                acc1[u*4+1] = fmaf(wv1, xv.y, acc1[u*4+1]);
                acc1[u*4+2] = fmaf(wv1, xv.z, acc1[u*4+2]);
                acc1[u*4+3] = fmaf(wv1, xv.w, acc1[u*4+3]);
            }
        }
        __syncthreads();
    }

    {
        float s0 = g1[mlo] * rsqrtf(v1[mlo] + EPSF);
        float bb0 = b1[mlo] - mu1[mlo] * s0;
        float s1 = g1[mlo + 128] * rsqrtf(v1[mlo + 128] + EPSF);
        float bb1 = b1[mlo + 128] - mu1[mlo + 128] * s1;
#pragma unroll
        for (int j = 0; j < 16; j++) {
            acc0[j] = fmaf(acc0[j], s0, bb0);
            acc1[j] = fmaf(acc1[j], s1, bb1);
        }
    }

    {
        float a00 = aw[mlo], a01 = aw[mlo + 128];
        float a10 = aw[256 + mlo], a11 = aw[256 + mlo + 128];
        float a20 = aw[512 + mlo], a21 = aw[512 + mlo + 128];
        float a30 = aw[768 + mlo], a31 = aw[768 + mlo + 128];
#pragma unroll
        for (int j = 0; j < 16; j++) {
            int p = pb + j;
            float yv0 = yu_s[mlo * 33 + p];
            float yv1 = yu_s[(mlo + 128) * 33 + p];
            float t0 = a00 * acc0[j] + a01 * acc1[j] + a10 * yv0 + a11 * yv1;
            float t1 = a20 * acc0[j] + a21 * acc1[j] + a30 * yv0 + a31 * yv1;
#pragma unroll
            for (int o = 16; o > 0; o >>= 1) {
                t0 += __shfl_xor_sync(0xffffffffu, t0, o);
                t1 += __shfl_xor_sync(0xffffffffu, t1, o);
            }
            if (lane == 0) {
                red[(wid * 16 + j) * 2 + 0] = t0;
                red[(wid * 16 + j) * 2 + 1] = t1;
            }
        }
    }
    __syncthreads();
    if (tid < 32) {
        int grp = tid >> 4, j = tid & 15;
        float s0 = 0.f, s1 = 0.f;
#pragma unroll
        for (int w = 0; w < 4; w++) {
            s0 += red[((grp * 4 + w) * 16 + j) * 2 + 0];
            s1 += red[((grp * 4 + w) * 16 + j) * 2 + 1];
        }
        zs[tid]      = 1.f / (1.f + expf(-(s0 + attb[0])));
        zs[32 + tid] = 1.f / (1.f + expf(-(s1 + attb[1])));
    }
    __syncthreads();

    float* xo0 = xf_nchw + ((size_t)(n * 256 + mlo)) * P_ + p0 + pb;
    float* xo1 = xf_nchw + ((size_t)(n * 256 + mlo + 128)) * P_ + p0 + pb;
    float* nh  = g_nhwc + ((size_t)n * P_ + p0 + pb) * 256;
#pragma unroll
    for (int j = 0; j < 16; j++) {
        int p = pb + j;
        float z0 = zs[p], z1 = zs[32 + p];
        float f0 = fmaf(acc0[j], z0, yu_s[mlo * 33 + p] * z1);
        float f1 = fmaf(acc1[j], z0, yu_s[(mlo + 128) * 33 + p] * z1);
        xo0[j] = f0;
        xo1[j] = f1;
        nh[(size_t)j * 256 + mlo] = f0;
        nh[(size_t)j * 256 + mlo + 128] = f1;
    }
}

// ---------------------------------------------------------------------------
// Kernel 2: offset conv3x3 (256 -> 18), pad 1. (unchanged from R2)
// ---------------------------------------------------------------------------
__global__ __launch_bounds__(256, 4)
void k2_off(const float* __restrict__ xf, const float* __restrict__ ow)
{
    __shared__ float xr[32 * 3 * 60];
    __shared__ float wr[18 * 289];

    const int h = blockIdx.x, n = blockIdx.y;
    const int tid = threadIdx.x;
    const int o = tid / 14, wg = tid % 14, wbase = wg * 4;

    float acc[4] = {0.f, 0.f, 0.f, 0.f};

    for (int c0 = 0; c0 < 256; c0 += 32) {
        for (int i = tid; i < 5568; i += 256) {
            int c = i / 174, rem = i % 174, r = rem / 58, colp = rem % 58;
            int row = h + r - 1, col = colp - 1;
            float v = 0.f;
            if (row >= 0 && row < 56 && col >= 0 && col < 56)
                v = xf[((size_t)(n * 256 + c0 + c)) * P_ + row * 56 + col];
            xr[c * 180 + r * 60 + colp] = v;
        }
        for (int i = tid; i < 5184; i += 256) {
            int oo = i / 288, rem = i % 288;
            wr[oo * 289 + rem] = ow[(size_t)oo * 2304 + c0 * 9 + rem];
        }
        __syncthreads();
        if (tid < 252) {
            for (int c = 0; c < 32; c++) {
#pragma unroll
                for (int ky = 0; ky < 3; ky++) {
                    const float4* rp = (const float4*)(xr + c * 180 + ky * 60 + wbase);
                    float4 A = rp[0], B = rp[1];
                    float xrow[6] = {A.x, A.y, A.z, A.w, B.x, B.y};
#pragma unroll
                    for (int kx = 0; kx < 3; kx++) {
                        float wv = wr[o * 289 + c * 9 + ky * 3 + kx];
#pragma unroll
                        for (int j = 0; j < 4; j++)
                            acc[j] = fmaf(wv, xrow[kx + j], acc[j]);
                    }
                }
            }
        }
        __syncthreads();
    }
    if (tid < 252) {
        float* ob = g_off + ((size_t)(n * 18 + o)) * P_ + h * 56 + wbase;
#pragma unroll
        for (int j = 0; j < 4; j++) ob[j] = acc[j];
    }
}

// ---------------------------------------------------------------------------
// Kernel 3: deformable conv via mma.sync tf32, software-pipelined.
// Block = 512 threads, tile = 64 px x 256 o; grid (49, 8) (3136 = 49*64).
// 72 chunks of (tap kk, 32 ch). Weights via cp.async.cg (no reg staging);
// gather LDGs issued BEFORE the chunk's MMAs so MMA latency hides them.
// Warp (g,h): o in [g*32,g*32+32), px in [h*32, h*32+32).
// ---------------------------------------------------------------------------
#define W_PITCH 36
#define S_PITCH 36
#define W_BUF_FLOATS (256 * W_PITCH)   // 9216
#define S_BUF_FLOATS (64 * S_PITCH)    // 2304
#define OFS_W    0                           // 2 x 9216 = 18432
#define OFS_S    (OFS_W + 2 * W_BUF_FLOATS)  // 2 x 2304 = 4608
#define OFS_MW   (OFS_S + 2 * S_BUF_FLOATS)  // 576*4 = 2304
#define OFS_MO   (OFS_MW + 2304)             // 2304
#define S3_FLOATS (OFS_MO + 2304)            // 27648 floats = 110592 B

__global__ __launch_bounds__(512, 1)
void k3_mma(const float* __restrict__ g2, const float* __restrict__ b2,
            const float* __restrict__ mu2, const float* __restrict__ v2,
            float* __restrict__ out)
{
    extern __shared__ float smf[];
    float*  wbuf = smf + OFS_W;
    float*  sbuf = smf + OFS_S;
    float4* mw4  = (float4*)(smf + OFS_MW);
    int4*   mo4  = (int4*)(smf + OFS_MO);
    const uint32_t sW = smem_u32(smf + OFS_W);

    const int n   = blockIdx.y;
    const int p0  = blockIdx.x * 64;
    const int tid = threadIdx.x;
    const int wid = tid >> 5;
    const int lane = tid & 31;

    // bilinear metadata: 64 px x 9 taps = 576 entries
    for (int e = tid; e < 576; e += 512) {
        int p = e / 9, k = e - p * 9;
        int pg = p0 + p;
        int ph = pg / 56, pw = pg % 56;
        float dy = g_off[((size_t)(n * 18 + 2 * k)) * P_ + pg];
        float dx = g_off[((size_t)(n * 18 + 2 * k + 1)) * P_ + pg];
        float sy = (float)(ph - 1 + k / 3) + dy;
        float sx = (float)(pw - 1 + k % 3) + dx;
        float y0f = floorf(sy), x0f = floorf(sx);
        float wy1 = sy - y0f, wx1 = sx - x0f;
        int iy0 = (int)y0f, ix0 = (int)x0f;
        bool vy0 = (iy0 >= 0) && (iy0 <= 55);
        bool vy1 = (iy0 + 1 >= 0) && (iy0 + 1 <= 55);
        bool vx0 = (ix0 >= 0) && (ix0 <= 55);
        bool vx1 = (ix0 + 1 >= 0) && (ix0 + 1 <= 55);
        int y0c = min(max(iy0, 0), 55),     y1c = min(max(iy0 + 1, 0), 55);
        int x0c = min(max(ix0, 0), 55),     x1c = min(max(ix0 + 1, 0), 55);
        float4 w;
        w.x = (vy0 && vx0) ? (1.f - wy1) * (1.f - wx1) : 0.f;
        w.y = (vy0 && vx1) ? (1.f - wy1) * wx1 : 0.f;
        w.z = (vy1 && vx0) ? wy1 * (1.f - wx1) : 0.f;
        w.w = (vy1 && vx1) ? wy1 * wx1 : 0.f;
        int4 oo;
        oo.x = (y0c * 56 + x0c) * 256;
        oo.y = (y0c * 56 + x1c) * 256;
        oo.z = (y1c * 56 + x0c) * 256;
        oo.w = (y1c * 56 + x1c) * 256;
        mw4[e] = w;
        mo4[e] = oo;
    }
    __syncthreads();

    const float* nh = g_nhwc + (size_t)n * P_ * 256;
    const int gidx = wid >> 1;          // o-group 0..7
    const int hidx = wid & 1;           // px-half 0..1
    const int o0  = gidx * 32;
    const int px0 = hidx * 32;
    const int qrow = lane >> 2;         // 0..7
    const int qcol = lane & 3;          // 0..3

    // weight cp.async mapping: thread -> o row, 4x16B segments
    const int w_o   = tid >> 1;         // 0..255
    const int w_sg  = (tid & 1) * 4;    // 0 or 4

    float acc[2][4][4];
#pragma unroll
    for (int m = 0; m < 2; m++)
#pragma unroll
        for (int t = 0; t < 4; t++)
#pragma unroll
            for (int c = 0; c < 4; c++) acc[m][t][c] = 0.f;

    float st[16];

    auto weights_issue = [&](int buf, int kk, int c0) {
        const float* src = g_wt + (size_t)w_o * 2304 + kk * 256 + c0 + w_sg * 4;
        uint32_t dst = sW + (buf * W_BUF_FLOATS + w_o * W_PITCH + w_sg * 4) * 4;
#pragma unroll
        for (int i = 0; i < 4; i++)
            cp_async16(dst + i * 16, src + i * 4);
        CP_COMMIT();
    };
    auto gather_issue = [&](int kk) {
        const int ci_base = lane;   // channel-local; c0 added via pointer
#pragma unroll
        for (int i = 0; i < 4; i++) {
            int p = wid * 4 + i;
            int4 oo = mo4[p * 9 + kk];
            st[i*4+0] = nh[oo.x + ci_base];
            st[i*4+1] = nh[oo.y + ci_base];
            st[i*4+2] = nh[oo.z + ci_base];
            st[i*4+3] = nh[oo.w + ci_base];
        }
    };
    auto gather_issue_c = [&](int kk, int c0) {
        const int ci = c0 + lane;
#pragma unroll
        for (int i = 0; i < 4; i++) {
            int p = wid * 4 + i;
            int4 oo = mo4[p * 9 + kk];
            st[i*4+0] = nh[oo.x + ci];
            st[i*4+1] = nh[oo.y + ci];
            st[i*4+2] = nh[oo.z + ci];
            st[i*4+3] = nh[oo.w + ci];
        }
    };
    auto gather_combine = [&](int buf, int kk) {
        float* dst = sbuf + buf * S_BUF_FLOATS;
#pragma unroll
        for (int i = 0; i < 4; i++) {
            int p = wid * 4 + i;
            float4 w = mw4[p * 9 + kk];
            float v = w.x * st[i*4+0] + w.y * st[i*4+1]
                    + w.z * st[i*4+2] + w.w * st[i*4+3];
            dst[p * S_PITCH + lane] = to_tf32(v);
        }
    };
    auto do_mma = [&](int buf) {
        const float* Wb = wbuf + buf * W_BUF_FLOATS;
        const float* Sb = sbuf + buf * S_BUF_FLOATS;
#pragma unroll
        for (int s = 0; s < 4; s++) {
            int k0 = s * 8;
            uint32_t a[2][4];
            const float* wr = Wb + (o0 + qrow) * W_PITCH + k0 + qcol;
#pragma unroll
            for (int m = 0; m < 2; m++) {
                const float* wm = wr + m * 16 * W_PITCH;
                a[m][0] = __float_as_uint(wm[0]);
                a[m][1] = __float_as_uint(wm[8 * W_PITCH]);
                a[m][2] = __float_as_uint(wm[4]);
                a[m][3] = __float_as_uint(wm[8 * W_PITCH + 4]);
            }
            uint32_t bb[4][2];
            const float* sr = Sb + (px0 + qrow) * S_PITCH + k0 + qcol;
#pragma unroll
            for (int t = 0; t < 4; t++) {
                bb[t][0] = __float_as_uint(sr[t * 8 * S_PITCH]);
                bb[t][1] = __float_as_uint(sr[t * 8 * S_PITCH + 4]);
            }
#pragma unroll
            for (int m = 0; m < 2; m++)
#pragma unroll
                for (int t = 0; t < 4; t++)
                    mma_tf32(acc[m][t], a[m], bb[t]);
        }
    };

    // prologue: chunk 0 into buf 0
    weights_issue(0, 0, 0);
    gather_issue(0);
    gather_combine(0, 0);
    CP_WAIT0();
    __syncthreads();

    for (int ch = 0; ch < 72; ch++) {
        int b = ch & 1;
        bool more = (ch + 1 < 72);
        int kkN = (ch + 1) >> 3, cbN = ((ch + 1) & 7) * 32;
        if (more) {
            weights_issue(b ^ 1, kkN, cbN);
            gather_issue_c(kkN, cbN);
        }
        do_mma(b);
        if (more) {
            gather_combine(b ^ 1, kkN);
            CP_WAIT0();
        }
        __syncthreads();
    }

    // epilogue: BN2 + store (float2 per (o, t))
#pragma unroll
    for (int m = 0; m < 2; m++) {
#pragma unroll
        for (int rh = 0; rh < 2; rh++) {
            int o = o0 + m * 16 + rh * 8 + qrow;
            float sc = g2[o] * rsqrtf(v2[o] + EPSF);
            float bi = b2[o] - mu2[o] * sc;
            float* ob = out + ((size_t)(n * 256 + o)) * P_ + p0 + px0;
#pragma unroll
            for (int t = 0; t < 4; t++) {
                float2 v;
                v.x = fmaf(acc[m][t][rh * 2 + 0], sc, bi);
                v.y = fmaf(acc[m][t][rh * 2 + 1], sc, bi);
                *(float2*)(ob + t * 8 + 2 * qcol) = v;
            }
        }
    }
}

// ---------------------------------------------------------------------------
extern "C" void kernel_launch(void* const* d_in, const int* in_sizes, int n_in,
                              void* d_out, int out_size)
{
    const float* x       = (const float*)d_in[0];
    const float* y       = (const float*)d_in[1];
    const float* conv1_w = (const float*)d_in[2];
    const float* bn1_g   = (const float*)d_in[3];
    const float* bn1_b   = (const float*)d_in[4];
    const float* bn1_m   = (const float*)d_in[5];
    const float* bn1_v   = (const float*)d_in[6];
    const float* att_w   = (const float*)d_in[7];
    const float* att_b   = (const float*)d_in[8];
    const float* off_w   = (const float*)d_in[9];
    const float* dcn_w   = (const float*)d_in[10];
    const float* bn2_g   = (const float*)d_in[11];
    const float* bn2_b   = (const float*)d_in[12];
    const float* bn2_m   = (const float*)d_in[13];
    const float* bn2_v   = (const float*)d_in[14];

    float* out = (float*)d_out;
    const size_t one = (size_t)N_ * OUTC * P_;  // 6,422,528

    float* xf_nchw;
    if ((size_t)out_size >= 2 * one) {
        xf_nchw = out + one;  // tuple (out, xf) flattened
    } else {
        void* p = nullptr;
        cudaGetSymbolAddress(&p, g_xf_scratch);
        xf_nchw = (float*)p;
    }

    cudaFuncSetAttribute(k1_fuse, cudaFuncAttributeMaxDynamicSharedMemorySize, 64 * 1024);
    cudaFuncSetAttribute(k3_mma,  cudaFuncAttributeMaxDynamicSharedMemorySize, S3_FLOATS * 4);

    k0_wt<<<256, 256>>>(dcn_w);

    const size_t smem1 = (512 + 4352 + 8448 + 1024 + 256 + 64) * 4; // 58,624
    k1_fuse<<<dim3(98, 8), 256, smem1>>>(x, y, conv1_w, bn1_g, bn1_b, bn1_m, bn1_v,
                                         att_w, att_b, xf_nchw);

    k2_off<<<dim3(56, 8), 256>>>(xf_nchw, off_w);

    k3_mma<<<dim3(49, 8), 512, S3_FLOATS * 4>>>(bn2_g, bn2_b, bn2_m, bn2_v, out);
}